// round 8
// baseline (speedup 1.0000x reference)
#include <cuda_runtime.h>
#include <cuda_bf16.h>
#include <cooperative_groups.h>
#include <cstdint>

namespace cg = cooperative_groups;

// Problem constants (fixed by the dataset)
#define BB    8        // batch
#define TT    4096     // time steps
#define FF    512      // input features
#define CC    128      // reduced input
#define UU    256      // LSTM units
#define OO    64       // output features
#define G4    1024     // 4*U

// -------- scratch (device globals; no allocation allowed) --------
__device__ float g_xr[(size_t)BB * TT * CC];   // 16 MB
__device__ float g_z [(size_t)BB * TT * G4];   // 128 MB
__device__ float g_hs[(size_t)BB * TT * UU];   // 32 MB

// ---------------- packed f32x2 helpers ----------------
__device__ __forceinline__ unsigned long long packf2(float lo, float hi) {
    unsigned long long r;
    asm("mov.b64 %0, {%1, %2};" : "=l"(r) : "f"(lo), "f"(hi));
    return r;
}
__device__ __forceinline__ void fma2(unsigned long long& d,
                                     unsigned long long a,
                                     unsigned long long b) {
    asm("fma.rn.f32x2 %0, %1, %2, %0;" : "+l"(d) : "l"(a), "l"(b));
}
__device__ __forceinline__ float reduce2(unsigned long long d) {
    float lo, hi;
    asm("mov.b64 {%0, %1}, %2;" : "=f"(lo), "=f"(hi) : "l"(d));
    return lo + hi;
}

// ---------------- fast activations ----------------
__device__ __forceinline__ float fsig(float x) {
    return 1.0f / (1.0f + __expf(-x));
}
__device__ __forceinline__ float ftanh(float x) {
    x = fminf(fmaxf(x, -15.0f), 15.0f);
    float e = __expf(2.0f * x);
    return (e - 1.0f) / (e + 1.0f);
}

// =====================================================================
// Generic fp32 tiled GEMM: C[M,N] = A[M,K] * B[K,N] + bias[N]
// (EXACT R1 configuration — BK=8 — measured-good)
// =====================================================================
template <int BM, int BN, int BK, int TM, int TN, int NT>
__global__ void __launch_bounds__(NT)
gemm_bias_kernel(const float* __restrict__ A, const float* __restrict__ Bm,
                 const float* __restrict__ bias, float* __restrict__ C,
                 int M, int N, int K) {
    __shared__ __align__(16) float As[BK][BM];
    __shared__ __align__(16) float Bs[BK][BN];

    const int tx = threadIdx.x % (BN / TN);
    const int ty = threadIdx.x / (BN / TN);
    const int rowBase = blockIdx.y * BM;
    const int colBase = blockIdx.x * BN;

    float acc[TM][TN];
#pragma unroll
    for (int i = 0; i < TM; i++)
#pragma unroll
        for (int j = 0; j < TN; j++) acc[i][j] = 0.0f;

    for (int k0 = 0; k0 < K; k0 += BK) {
#pragma unroll 2
        for (int idx = threadIdx.x; idx < BM * BK / 4; idx += NT) {
            int r  = idx / (BK / 4);
            int kc = (idx % (BK / 4)) * 4;
            float4 v = *(const float4*)&A[(size_t)(rowBase + r) * K + k0 + kc];
            As[kc + 0][r] = v.x;
            As[kc + 1][r] = v.y;
            As[kc + 2][r] = v.z;
            As[kc + 3][r] = v.w;
        }
#pragma unroll 2
        for (int idx = threadIdx.x; idx < BK * BN / 4; idx += NT) {
            int kr = idx / (BN / 4);
            int cc = (idx % (BN / 4)) * 4;
            *(float4*)&Bs[kr][cc] =
                *(const float4*)&Bm[(size_t)(k0 + kr) * N + colBase + cc];
        }
        __syncthreads();

#pragma unroll
        for (int kk = 0; kk < BK; kk++) {
            float ra[TM], rb[TN];
#pragma unroll
            for (int i = 0; i < TM; i++) ra[i] = As[kk][ty * TM + i];
#pragma unroll
            for (int j = 0; j < TN; j++) rb[j] = Bs[kk][tx * TN + j];
#pragma unroll
            for (int i = 0; i < TM; i++)
#pragma unroll
                for (int j = 0; j < TN; j++)
                    acc[i][j] = fmaf(ra[i], rb[j], acc[i][j]);
        }
        __syncthreads();
    }

#pragma unroll
    for (int i = 0; i < TM; i++) {
        int row = rowBase + ty * TM + i;
#pragma unroll
        for (int j = 0; j < TN; j += 4) {
            int col = colBase + tx * TN + j;
            float4 b4 = *(const float4*)&bias[col];
            float4 o;
            o.x = acc[i][j + 0] + b4.x;
            o.y = acc[i][j + 1] + b4.y;
            o.z = acc[i][j + 2] + b4.z;
            o.w = acc[i][j + 3] + b4.w;
            *(float4*)&C[(size_t)row * N + col] = o;
        }
    }
}

// =====================================================================
// LSTM recurrence — batch-amortized sync.
// 2 clusters x 8 CTAs x 256 threads. Each cluster advances FOUR batch
// recurrences per step with ONE cluster.sync (sync cost amortized 4x).
// Weights (128 gate-cols x 256) live once in registers, reused by all
// 4 batches. R1's proven layout: c = tid&127, s = tid>>7 (K-half is
// warp-uniform -> broadcast LDS). Dot = 4 independent FFMA2 chains
// (one per batch). Epilogue spread over warps 4..7: warp 4+b owns
// batch b's cell state, h update, and DSMEM pushes.
// =====================================================================
#define LSTM_NTH 256
#define CLSZ     8
#define BPC      4     // batches per cluster
#define NCLUS    (BB / BPC)   // 2

__global__ void __cluster_dims__(CLSZ, 1, 1) __launch_bounds__(LSTM_NTH, 1)
lstm_kernel(const float* __restrict__ rec_kernel) {
    cg::cluster_group cluster = cg::this_cluster();
    const int rank  = cluster.block_rank();            // 0..7
    const int cbase = (blockIdx.x / CLSZ) * BPC;       // first batch of cluster
    const int tid   = threadIdx.x;
    const int lane  = tid & 31;
    const int wid   = tid >> 5;

    const int c  = tid & 127;   // gate-column within this CTA's 128 cols
    const int s  = tid >> 7;    // K-half (warp-uniform)
    const int g  = c >> 5;      // gate: 0=i,1=f,2=g,3=o
    const int lu = c & 31;      // local unit
    const int colIdx = (g << 8) + rank * 32 + lu;

    __shared__ __align__(16) float hbuf[BPC][2][UU];   // 8 KB
    __shared__ float part[BPC][2][128];                // 4 KB
    __shared__ float act[BPC][128];                    // 2 KB

    // ---- weight slice into registers (R1 indexing), shared by all batches ----
    unsigned long long w2[64];
#pragma unroll
    for (int m = 0; m < 64; m++) {
        float a = rec_kernel[(size_t)(s * 128 + 2 * m)     * G4 + colIdx];
        float b = rec_kernel[(size_t)(s * 128 + 2 * m + 1) * G4 + colIdx];
        w2[m] = packf2(a, b);
    }

    // Epilogue warps (4..7): base DSMEM pointer per peer; batch/buffer offset
    // added as element offset ((b*2+q)*UU) since hbuf is contiguous.
    float* dstBase[CLSZ];
    if (wid >= 4) {
#pragma unroll
        for (int r = 0; r < CLSZ; r++)
            dstBase[r] = (float*)cluster.map_shared_rank(
                             (void*)&hbuf[0][0][rank * 32 + lane], r);
    }

    // zero all h buffers
    for (int i = tid; i < BPC * 2 * UU; i += LSTM_NTH) ((float***)nullptr, ((float*)hbuf)[i] = 0.0f);
    cluster.sync();   // buffers zeroed cluster-wide

    // per-batch z pointers and prefetch (held by tid<128, i.e. s==0)
    const float* zb[BPC];
    float zin[BPC];
#pragma unroll
    for (int b = 0; b < BPC; b++) {
        zb[b] = g_z + (size_t)(cbase + b) * TT * G4 + colIdx;
        zin[b] = (s == 0) ? zb[b][0] : 0.0f;
    }

    // epilogue warps: cell state for their batch
    float cst = 0.0f;
    const int eb = wid - 4;     // batch owned by this epilogue warp (if wid>=4)
    float* hsb = (wid >= 4)
        ? g_hs + (size_t)(cbase + eb) * TT * UU + rank * 32 + lane
        : nullptr;

#pragma unroll 1
    for (int t = 0; t < TT; t++) {
        const int p = t & 1;

        // ---- dots: 4 independent chains, one per batch (w2 reused) ----
        unsigned long long acc[BPC] = {0ULL, 0ULL, 0ULL, 0ULL};
        const ulonglong2* hb0 = (const ulonglong2*)hbuf[0][p];
        const ulonglong2* hb1 = (const ulonglong2*)hbuf[1][p];
        const ulonglong2* hb2 = (const ulonglong2*)hbuf[2][p];
        const ulonglong2* hb3 = (const ulonglong2*)hbuf[3][p];
#pragma unroll
        for (int m = 0; m < 32; m++) {
            const int idx = s * 32 + m;
            ulonglong2 h0 = hb0[idx];
            ulonglong2 h1 = hb1[idx];
            ulonglong2 h2 = hb2[idx];
            ulonglong2 h3 = hb3[idx];
            fma2(acc[0], w2[2 * m], h0.x);  fma2(acc[0], w2[2 * m + 1], h0.y);
            fma2(acc[1], w2[2 * m], h1.x);  fma2(acc[1], w2[2 * m + 1], h1.y);
            fma2(acc[2], w2[2 * m], h2.x);  fma2(acc[2], w2[2 * m + 1], h2.y);
            fma2(acc[3], w2[2 * m], h3.x);  fma2(acc[3], w2[2 * m + 1], h3.y);
        }
#pragma unroll
        for (int b = 0; b < BPC; b++)
            part[b][s][c] = reduce2(acc[b]);
        __syncthreads();

        // ---- gate activations (warps 0-3) ----
        if (s == 0) {
#pragma unroll
            for (int b = 0; b < BPC; b++) {
                float z = part[b][0][c] + part[b][1][c] + zin[b];
                if (t + 1 < TT) zin[b] = __ldg(&zb[b][(size_t)(t + 1) * G4]);
                act[b][c] = (g == 2) ? ftanh(z) : fsig(z);
            }
        }
        __syncthreads();

        // ---- state update + h distribution (warps 4-7, one batch each) ----
        if (wid >= 4) {
            float ai = act[eb][lane];
            float af = act[eb][32 + lane];
            float ag = act[eb][64 + lane];
            float ao = act[eb][96 + lane];
            cst = af * cst + ai * ag;
            float hval = ao * ftanh(cst);
            const int q = p ^ 1;
            const int off = (eb * 2 + q) * UU;   // element offset into peer hbuf
#pragma unroll
            for (int r = 0; r < CLSZ; r++)
                dstBase[r][off] = hval;          // DSMEM stores, released by sync
            hsb[(size_t)t * UU] = hval;
        }
        cluster.sync();                          // ONE sync per 4 batch-steps
    }
}

// =====================================================================
// Launch
// =====================================================================
extern "C" void kernel_launch(void* const* d_in, const int* in_sizes, int n_in,
                              void* d_out, int out_size) {
    const float* x          = (const float*)d_in[0];
    const float* w_in       = (const float*)d_in[1];
    const float* b_in       = (const float*)d_in[2];
    const float* kern       = (const float*)d_in[3];
    const float* rec_kernel = (const float*)d_in[4];
    const float* bias       = (const float*)d_in[5];
    const float* w_out      = (const float*)d_in[6];
    const float* b_out      = (const float*)d_in[7];
    float* out = (float*)d_out;

    float* xr = nullptr;
    float* zz = nullptr;
    float* hs = nullptr;
    cudaGetSymbolAddress((void**)&xr, g_xr);
    cudaGetSymbolAddress((void**)&zz, g_z);
    cudaGetSymbolAddress((void**)&hs, g_hs);

    const int M = BB * TT;  // 32768

    gemm_bias_kernel<128, 128, 8, 8, 8, 256>
        <<<dim3(CC / 128, M / 128), 256>>>(x, w_in, b_in, xr, M, CC, FF);

    gemm_bias_kernel<128, 128, 8, 8, 8, 256>
        <<<dim3(G4 / 128, M / 128), 256>>>(xr, kern, bias, zz, M, G4, CC);

    lstm_kernel<<<NCLUS * CLSZ, LSTM_NTH>>>(rec_kernel);

    gemm_bias_kernel<128, 64, 8, 8, 4, 256>
        <<<dim3(OO / 64, M / 128), 256>>>(hs, w_out, b_out, out, M, OO, UU);
}

// round 9
// speedup vs baseline: 2.0862x; 2.0862x over previous
#include <cuda_runtime.h>
#include <cuda_bf16.h>
#include <cooperative_groups.h>
#include <cstdint>

namespace cg = cooperative_groups;

// Problem constants (fixed by the dataset)
#define BB    8        // batch
#define TT    4096     // time steps
#define FF    512      // input features
#define CC    128      // reduced input
#define UU    256      // LSTM units
#define OO    64       // output features
#define G4    1024     // 4*U

// -------- scratch (device globals; no allocation allowed) --------
__device__ float g_xr[(size_t)BB * TT * CC];   // 16 MB
__device__ float g_z [(size_t)BB * TT * G4];   // 128 MB
__device__ float g_hs[(size_t)BB * TT * UU];   // 32 MB

// ---------------- packed f32x2 helpers ----------------
__device__ __forceinline__ unsigned long long packf2(float lo, float hi) {
    unsigned long long r;
    asm("mov.b64 %0, {%1, %2};" : "=l"(r) : "f"(lo), "f"(hi));
    return r;
}
__device__ __forceinline__ void fma2(unsigned long long& d,
                                     unsigned long long a,
                                     unsigned long long b) {
    asm("fma.rn.f32x2 %0, %1, %2, %0;" : "+l"(d) : "l"(a), "l"(b));
}
__device__ __forceinline__ float reduce2(unsigned long long d) {
    float lo, hi;
    asm("mov.b64 {%0, %1}, %2;" : "=f"(lo), "=f"(hi) : "l"(d));
    return lo + hi;
}

// ---------------- fast activations ----------------
__device__ __forceinline__ float fsig(float x) {
    return 1.0f / (1.0f + __expf(-x));
}
__device__ __forceinline__ float ftanh(float x) {
    x = fminf(fmaxf(x, -15.0f), 15.0f);
    float e = __expf(2.0f * x);
    return (e - 1.0f) / (e + 1.0f);
}

// =====================================================================
// fp32 tiled GEMM with double-buffered SMEM pipeline:
//   C[M,N] = A[M,K] * B[K,N] + bias[N]
// Per k-tile: LDG tile k+1 -> regs, compute tile k, STS regs -> other
// buffer, ONE __syncthreads. As padded +4 floats (conflict-free
// transpose stores). Fragment loads vectorized (float4).
// Requires BM*BK/4 == NT, TM%4==0, TN%4==0.
// =====================================================================
template <int BM, int BN, int BK, int TM, int TN, int NT>
__global__ void __launch_bounds__(NT)
gemm_bias_kernel(const float* __restrict__ A, const float* __restrict__ Bm,
                 const float* __restrict__ bias, float* __restrict__ C,
                 int M, int N, int K) {
    static_assert(BM * BK / 4 == NT, "A-tile load = 1 float4/thread");
    __shared__ __align__(16) float As[2][BK][BM + 4];
    __shared__ __align__(16) float Bs[2][BK][BN];

    const int tid = threadIdx.x;
    const int tx = tid % (BN / TN);
    const int ty = tid / (BN / TN);
    const int rowBase = blockIdx.y * BM;
    const int colBase = blockIdx.x * BN;

    // A-tile loader coords (1 float4 per thread)
    const int ar  = tid / (BK / 4);
    const int akc = (tid % (BK / 4)) * 4;
    // B-tile loader coords (<=1 float4 per thread, predicated)
    const bool bAct = tid < (BK * BN / 4);
    const int br  = bAct ? tid / (BN / 4) : 0;
    const int bcc = bAct ? (tid % (BN / 4)) * 4 : 0;

    const float* aSrc = A + (size_t)(rowBase + ar) * K + akc;
    const float* bSrc = Bm + (size_t)br * N + colBase + bcc;

    float acc[TM][TN];
#pragma unroll
    for (int i = 0; i < TM; i++)
#pragma unroll
        for (int j = 0; j < TN; j++) acc[i][j] = 0.0f;

    const int nk = K / BK;

    // prologue: load + store tile 0
    float4 va = *(const float4*)aSrc;
    float4 vb = bAct ? *(const float4*)bSrc : make_float4(0, 0, 0, 0);
    As[0][akc + 0][ar] = va.x;
    As[0][akc + 1][ar] = va.y;
    As[0][akc + 2][ar] = va.z;
    As[0][akc + 3][ar] = va.w;
    if (bAct) *(float4*)&Bs[0][br][bcc] = vb;
    __syncthreads();

#pragma unroll 1
    for (int kt = 0; kt < nk; kt++) {
        const int cur = kt & 1;
        // issue LDG for tile kt+1 (latency hidden behind compute)
        if (kt + 1 < nk) {
            va = *(const float4*)(aSrc + (size_t)(kt + 1) * BK);
            if (bAct) vb = *(const float4*)(bSrc + (size_t)(kt + 1) * BK * N);
        }

        // compute tile kt from buffer cur
#pragma unroll
        for (int kk = 0; kk < BK; kk++) {
            float ra[TM], rb[TN];
#pragma unroll
            for (int i = 0; i < TM; i += 4)
                *(float4*)&ra[i] = *(const float4*)&As[cur][kk][ty * TM + i];
#pragma unroll
            for (int j = 0; j < TN; j += 4)
                *(float4*)&rb[j] = *(const float4*)&Bs[cur][kk][tx * TN + j];
#pragma unroll
            for (int i = 0; i < TM; i++)
#pragma unroll
                for (int j = 0; j < TN; j++)
                    acc[i][j] = fmaf(ra[i], rb[j], acc[i][j]);
        }

        // stage tile kt+1 into the other buffer
        if (kt + 1 < nk) {
            const int nxt = cur ^ 1;
            As[nxt][akc + 0][ar] = va.x;
            As[nxt][akc + 1][ar] = va.y;
            As[nxt][akc + 2][ar] = va.z;
            As[nxt][akc + 3][ar] = va.w;
            if (bAct) *(float4*)&Bs[nxt][br][bcc] = vb;
            __syncthreads();
        }
    }

    // epilogue with bias, vectorized
#pragma unroll
    for (int i = 0; i < TM; i++) {
        int row = rowBase + ty * TM + i;
#pragma unroll
        for (int j = 0; j < TN; j += 4) {
            int col = colBase + tx * TN + j;
            float4 b4 = *(const float4*)&bias[col];
            float4 o;
            o.x = acc[i][j + 0] + b4.x;
            o.y = acc[i][j + 1] + b4.y;
            o.z = acc[i][j + 2] + b4.z;
            o.w = acc[i][j + 3] + b4.w;
            *(float4*)&C[(size_t)row * N + col] = o;
        }
    }
}

// =====================================================================
// LSTM recurrence — R1-EXACT mechanism and layout (the measured-best
// 4.1ms configuration), with ONE isolated change: the dot product uses
// 4 independent FFMA2 accumulator chains instead of a single 64-deep
// dependent chain. Everything else (c=tid&127, s=tid>>7 warp-uniform
// broadcast LDS, part[] two-phase reduction, two __syncthreads, warp-0
// epilogue with mapped-pointer DSMEM stores, one cluster.sync) is
// byte-for-byte R1.
// =====================================================================
#define LSTM_NTH 256
#define CLSZ     8

__global__ void __cluster_dims__(CLSZ, 1, 1) __launch_bounds__(LSTM_NTH, 1)
lstm_kernel(const float* __restrict__ rec_kernel) {
    cg::cluster_group cluster = cg::this_cluster();
    const int rank  = cluster.block_rank();        // 0..7 within cluster
    const int batch = blockIdx.x / CLSZ;           // 0..7
    const int tid   = threadIdx.x;

    const int c  = tid & 127;   // gate-column within this CTA's 128-col slice
    const int s  = tid >> 7;    // K-half: 0 -> k[0,128), 1 -> k[128,256)
    const int g  = c >> 5;      // gate: 0=i,1=f,2=g,3=o
    const int lu = c & 31;      // local unit
    const int u  = rank * 32 + lu;
    const int colIdx = (g << 8) + u;               // column in [0,1024)

    __shared__ __align__(16) float hbuf[2][UU];
    __shared__ float part[2][128];
    __shared__ float act[128];

    // ---- load weight slice into registers as packed pairs ----
    unsigned long long w2[64];
#pragma unroll
    for (int m = 0; m < 64; m++) {
        float a = rec_kernel[(size_t)(s * 128 + 2 * m)     * G4 + colIdx];
        float b = rec_kernel[(size_t)(s * 128 + 2 * m + 1) * G4 + colIdx];
        w2[m] = packf2(a, b);
    }

    // ---- precompute peer h-buffer pointers (used by warp 0) ----
    float* dst0[CLSZ];
    float* dst1[CLSZ];
#pragma unroll
    for (int r = 0; r < CLSZ; r++) {
        dst0[r] = (float*)cluster.map_shared_rank((void*)hbuf[0], r);
        dst1[r] = (float*)cluster.map_shared_rank((void*)hbuf[1], r);
    }

    // ---- init state ----
    for (int i = tid; i < 2 * UU; i += LSTM_NTH) ((float*)hbuf)[i] = 0.0f;
    float cst = 0.0f;   // cell state (meaningful in warp-0 lanes)
    cluster.sync();     // everyone's buffers zeroed before any remote write

    const float* zbase = g_z + (size_t)batch * TT * G4 + colIdx;
    float zin = (s == 0) ? zbase[0] : 0.0f;   // prefetch t=0
    float* hsbase = g_hs + (size_t)batch * TT * UU;

    int p = 0;
#pragma unroll 1
    for (int t = 0; t < TT; t++) {
        // ---- z_partial = h[p] (my K-half) dot my weight column ----
        // 4 independent accumulator chains (only change vs R1)
        unsigned long long a0 = 0ULL, a1 = 0ULL, a2 = 0ULL, a3 = 0ULL;
        const float4* h4 = (const float4*)hbuf[p];
#pragma unroll
        for (int m = 0; m < 32; m += 2) {
            float4 hv0 = h4[s * 32 + m];
            float4 hv1 = h4[s * 32 + m + 1];
            fma2(a0, w2[2 * m],     packf2(hv0.x, hv0.y));
            fma2(a1, w2[2 * m + 1], packf2(hv0.z, hv0.w));
            fma2(a2, w2[2 * m + 2], packf2(hv1.x, hv1.y));
            fma2(a3, w2[2 * m + 3], packf2(hv1.z, hv1.w));
        }
        part[s][c] = reduce2(a0) + reduce2(a1) + reduce2(a2) + reduce2(a3);
        __syncthreads();

        if (tid < 128) {
            float z = part[0][c] + part[1][c] + zin;
            if (t + 1 < TT) zin = zbase[(size_t)(t + 1) * G4];  // prefetch
            act[c] = (g == 2) ? ftanh(z) : fsig(z);
        }
        __syncthreads();

        if (tid < 32) {
            float ai = act[tid];
            float af = act[32 + tid];
            float ag = act[64 + tid];
            float ao = act[96 + tid];
            cst = af * cst + ai * ag;
            float hval = ao * ftanh(cst);
            int uw = rank * 32 + tid;
            hsbase[(size_t)t * UU + uw] = hval;
            float** dst = (p == 0) ? dst1 : dst0;   // write next buffer
#pragma unroll
            for (int r = 0; r < CLSZ; r++) dst[r][uw] = hval;
        }
        cluster.sync();   // release DSMEM h-writes, all CTAs step together
        p ^= 1;
    }
}

// =====================================================================
// Launch
// =====================================================================
extern "C" void kernel_launch(void* const* d_in, const int* in_sizes, int n_in,
                              void* d_out, int out_size) {
    const float* x          = (const float*)d_in[0];  // [8,4096,512]
    const float* w_in       = (const float*)d_in[1];  // [512,128]
    const float* b_in       = (const float*)d_in[2];  // [128]
    const float* kern       = (const float*)d_in[3];  // [128,1024]
    const float* rec_kernel = (const float*)d_in[4];  // [256,1024]
    const float* bias       = (const float*)d_in[5];  // [1024]
    const float* w_out      = (const float*)d_in[6];  // [256,64]
    const float* b_out      = (const float*)d_in[7];  // [64]
    float* out = (float*)d_out;                       // [8,4096,64]

    float* xr = nullptr;
    float* zz = nullptr;
    float* hs = nullptr;
    cudaGetSymbolAddress((void**)&xr, g_xr);
    cudaGetSymbolAddress((void**)&zz, g_z);
    cudaGetSymbolAddress((void**)&hs, g_hs);

    const int M = BB * TT;  // 32768

    // 1) xr = x @ w_in + b_in       [32768,512] x [512,128]
    gemm_bias_kernel<128, 128, 8, 8, 8, 256>
        <<<dim3(CC / 128, M / 128), 256>>>(x, w_in, b_in, xr, M, CC, FF);

    // 2) z = xr @ kernel + bias     [32768,128] x [128,1024]
    gemm_bias_kernel<128, 128, 8, 8, 8, 256>
        <<<dim3(G4 / 128, M / 128), 256>>>(xr, kern, bias, zz, M, G4, CC);

    // 3) LSTM recurrence: 8 clusters x 8 CTAs
    lstm_kernel<<<BB * CLSZ, LSTM_NTH>>>(rec_kernel);

    // 4) out = hs @ w_out + b_out   [32768,256] x [256,64]
    gemm_bias_kernel<128, 64, 8, 8, 4, 256>
        <<<dim3(OO / 64, M / 128), 256>>>(hs, w_out, b_out, out, M, OO, UU);
}

// round 10
// speedup vs baseline: 2.1207x; 1.0166x over previous
#include <cuda_runtime.h>
#include <cuda_bf16.h>
#include <cooperative_groups.h>
#include <cstdint>

namespace cg = cooperative_groups;

// Problem constants (fixed by the dataset)
#define BB    8        // batch
#define TT    4096     // time steps
#define FF    512      // input features
#define CC    128      // reduced input
#define UU    256      // LSTM units
#define OO    64       // output features
#define G4    1024     // 4*U

// -------- scratch (device globals; no allocation allowed) --------
__device__ float g_xr[(size_t)BB * TT * CC];   // 16 MB
__device__ float g_z [(size_t)BB * TT * G4];   // 128 MB
__device__ float g_hs[(size_t)BB * TT * UU];   // 32 MB

// ---------------- packed f32x2 helpers ----------------
__device__ __forceinline__ unsigned long long packf2(float lo, float hi) {
    unsigned long long r;
    asm("mov.b64 %0, {%1, %2};" : "=l"(r) : "f"(lo), "f"(hi));
    return r;
}
__device__ __forceinline__ void fma2(unsigned long long& d,
                                     unsigned long long a,
                                     unsigned long long b) {
    asm("fma.rn.f32x2 %0, %1, %2, %0;" : "+l"(d) : "l"(a), "l"(b));
}
__device__ __forceinline__ float reduce2(unsigned long long d) {
    float lo, hi;
    asm("mov.b64 {%0, %1}, %2;" : "=f"(lo), "=f"(hi) : "l"(d));
    return lo + hi;
}

// ---------------- fast activations (MUFU-based, ~1e-7 rel err) ----------------
__device__ __forceinline__ float fsig(float x) {
    return 1.0f / (1.0f + __expf(-x));
}
__device__ __forceinline__ float ftanh(float x) {
    x = fminf(fmaxf(x, -15.0f), 15.0f);
    float e = __expf(2.0f * x);
    return (e - 1.0f) / (e + 1.0f);
}

// =====================================================================
// fp32 tiled GEMM with double-buffered SMEM pipeline (R9, measured-good):
//   C[M,N] = A[M,K] * B[K,N] + bias[N]
// Per k-tile: LDG tile k+1 -> regs, compute tile k, STS regs -> other
// buffer, ONE __syncthreads. As padded +4 floats (conflict-free
// transpose stores). Fragment loads vectorized (float4).
// Requires BM*BK/4 == NT, TM%4==0, TN%4==0.
// =====================================================================
template <int BM, int BN, int BK, int TM, int TN, int NT>
__global__ void __launch_bounds__(NT)
gemm_bias_kernel(const float* __restrict__ A, const float* __restrict__ Bm,
                 const float* __restrict__ bias, float* __restrict__ C,
                 int M, int N, int K) {
    static_assert(BM * BK / 4 == NT, "A-tile load = 1 float4/thread");
    __shared__ __align__(16) float As[2][BK][BM + 4];
    __shared__ __align__(16) float Bs[2][BK][BN];

    const int tid = threadIdx.x;
    const int tx = tid % (BN / TN);
    const int ty = tid / (BN / TN);
    const int rowBase = blockIdx.y * BM;
    const int colBase = blockIdx.x * BN;

    // A-tile loader coords (1 float4 per thread)
    const int ar  = tid / (BK / 4);
    const int akc = (tid % (BK / 4)) * 4;
    // B-tile loader coords (<=1 float4 per thread, predicated)
    const bool bAct = tid < (BK * BN / 4);
    const int br  = bAct ? tid / (BN / 4) : 0;
    const int bcc = bAct ? (tid % (BN / 4)) * 4 : 0;

    const float* aSrc = A + (size_t)(rowBase + ar) * K + akc;
    const float* bSrc = Bm + (size_t)br * N + colBase + bcc;

    float acc[TM][TN];
#pragma unroll
    for (int i = 0; i < TM; i++)
#pragma unroll
        for (int j = 0; j < TN; j++) acc[i][j] = 0.0f;

    const int nk = K / BK;

    // prologue: load + store tile 0
    float4 va = *(const float4*)aSrc;
    float4 vb = bAct ? *(const float4*)bSrc : make_float4(0, 0, 0, 0);
    As[0][akc + 0][ar] = va.x;
    As[0][akc + 1][ar] = va.y;
    As[0][akc + 2][ar] = va.z;
    As[0][akc + 3][ar] = va.w;
    if (bAct) *(float4*)&Bs[0][br][bcc] = vb;
    __syncthreads();

#pragma unroll 1
    for (int kt = 0; kt < nk; kt++) {
        const int cur = kt & 1;
        // issue LDG for tile kt+1 (latency hidden behind compute)
        if (kt + 1 < nk) {
            va = *(const float4*)(aSrc + (size_t)(kt + 1) * BK);
            if (bAct) vb = *(const float4*)(bSrc + (size_t)(kt + 1) * BK * N);
        }

        // compute tile kt from buffer cur
#pragma unroll
        for (int kk = 0; kk < BK; kk++) {
            float ra[TM], rb[TN];
#pragma unroll
            for (int i = 0; i < TM; i += 4)
                *(float4*)&ra[i] = *(const float4*)&As[cur][kk][ty * TM + i];
#pragma unroll
            for (int j = 0; j < TN; j += 4)
                *(float4*)&rb[j] = *(const float4*)&Bs[cur][kk][tx * TN + j];
#pragma unroll
            for (int i = 0; i < TM; i++)
#pragma unroll
                for (int j = 0; j < TN; j++)
                    acc[i][j] = fmaf(ra[i], rb[j], acc[i][j]);
        }

        // stage tile kt+1 into the other buffer
        if (kt + 1 < nk) {
            const int nxt = cur ^ 1;
            As[nxt][akc + 0][ar] = va.x;
            As[nxt][akc + 1][ar] = va.y;
            As[nxt][akc + 2][ar] = va.z;
            As[nxt][akc + 3][ar] = va.w;
            if (bAct) *(float4*)&Bs[nxt][br][bcc] = vb;
            __syncthreads();
        }
    }

    // epilogue with bias, vectorized
#pragma unroll
    for (int i = 0; i < TM; i++) {
        int row = rowBase + ty * TM + i;
#pragma unroll
        for (int j = 0; j < TN; j += 4) {
            int col = colBase + tx * TN + j;
            float4 b4 = *(const float4*)&bias[col];
            float4 o;
            o.x = acc[i][j + 0] + b4.x;
            o.y = acc[i][j + 1] + b4.y;
            o.z = acc[i][j + 2] + b4.z;
            o.w = acc[i][j + 3] + b4.w;
            *(float4*)&C[(size_t)row * N + col] = o;
        }
    }
}

// =====================================================================
// LSTM recurrence — R1 BYTE-EXACT (the measured-best 4.1ms config).
// Grid = 64 CTAs = 8 clusters (one per batch) of 8 CTAs. Each CTA owns
// 32 units (128 gate columns), keeps its rec_kernel slice [256,128] in
// registers (256 thr x 64 f32x2 pairs), cell state in warp-0 lanes.
// h exchanged via DSMEM mapped-pointer stores, double-buffered, one
// cluster.sync per step.
// =====================================================================
#define LSTM_NTH 256
#define CLSZ     8

__global__ void __cluster_dims__(CLSZ, 1, 1) __launch_bounds__(LSTM_NTH, 1)
lstm_kernel(const float* __restrict__ rec_kernel) {
    cg::cluster_group cluster = cg::this_cluster();
    const int rank  = cluster.block_rank();        // 0..7 within cluster
    const int batch = blockIdx.x / CLSZ;           // 0..7
    const int tid   = threadIdx.x;

    const int c  = tid & 127;   // gate-column within this CTA's 128-col slice
    const int s  = tid >> 7;    // K-half: 0 -> k[0,128), 1 -> k[128,256)
    const int g  = c >> 5;      // gate: 0=i,1=f,2=g,3=o
    const int lu = c & 31;      // local unit
    const int u  = rank * 32 + lu;
    const int colIdx = (g << 8) + u;               // column in [0,1024)

    __shared__ __align__(16) float hbuf[2][UU];
    __shared__ float part[2][128];
    __shared__ float act[128];

    // ---- load weight slice into registers as packed pairs ----
    unsigned long long w2[64];
#pragma unroll
    for (int m = 0; m < 64; m++) {
        float a = rec_kernel[(size_t)(s * 128 + 2 * m)     * G4 + colIdx];
        float b = rec_kernel[(size_t)(s * 128 + 2 * m + 1) * G4 + colIdx];
        w2[m] = packf2(a, b);
    }

    // ---- precompute peer h-buffer pointers (used by warp 0) ----
    float* dst0[CLSZ];
    float* dst1[CLSZ];
#pragma unroll
    for (int r = 0; r < CLSZ; r++) {
        dst0[r] = (float*)cluster.map_shared_rank((void*)hbuf[0], r);
        dst1[r] = (float*)cluster.map_shared_rank((void*)hbuf[1], r);
    }

    // ---- init state ----
    for (int i = tid; i < 2 * UU; i += LSTM_NTH) ((float*)hbuf)[i] = 0.0f;
    float cst = 0.0f;   // cell state (meaningful in warp-0 lanes)
    cluster.sync();     // everyone's buffers zeroed before any remote write

    const float* zbase = g_z + (size_t)batch * TT * G4 + colIdx;
    float zin = (s == 0) ? zbase[0] : 0.0f;   // prefetch t=0
    float* hsbase = g_hs + (size_t)batch * TT * UU;

    int p = 0;
#pragma unroll 1
    for (int t = 0; t < TT; t++) {
        // ---- z_partial = h[p] (my K-half) dot my weight column ----
        unsigned long long acc2 = 0ULL;
        const float4* h4 = (const float4*)hbuf[p];
#pragma unroll
        for (int m = 0; m < 32; m++) {
            float4 hv = h4[s * 32 + m];
            fma2(acc2, w2[2 * m],     packf2(hv.x, hv.y));
            fma2(acc2, w2[2 * m + 1], packf2(hv.z, hv.w));
        }
        part[s][c] = reduce2(acc2);
        __syncthreads();

        if (tid < 128) {
            float z = part[0][c] + part[1][c] + zin;
            if (t + 1 < TT) zin = zbase[(size_t)(t + 1) * G4];  // prefetch
            act[c] = (g == 2) ? ftanh(z) : fsig(z);
        }
        __syncthreads();

        if (tid < 32) {
            float ai = act[tid];
            float af = act[32 + tid];
            float ag = act[64 + tid];
            float ao = act[96 + tid];
            cst = af * cst + ai * ag;
            float hval = ao * ftanh(cst);
            int uw = rank * 32 + tid;
            hsbase[(size_t)t * UU + uw] = hval;
            float** dst = (p == 0) ? dst1 : dst0;   // write next buffer
#pragma unroll
            for (int r = 0; r < CLSZ; r++) dst[r][uw] = hval;
        }
        cluster.sync();   // release DSMEM h-writes, all CTAs step together
        p ^= 1;
    }
}

// =====================================================================
// Launch
// =====================================================================
extern "C" void kernel_launch(void* const* d_in, const int* in_sizes, int n_in,
                              void* d_out, int out_size) {
    const float* x          = (const float*)d_in[0];  // [8,4096,512]
    const float* w_in       = (const float*)d_in[1];  // [512,128]
    const float* b_in       = (const float*)d_in[2];  // [128]
    const float* kern       = (const float*)d_in[3];  // [128,1024]
    const float* rec_kernel = (const float*)d_in[4];  // [256,1024]
    const float* bias       = (const float*)d_in[5];  // [1024]
    const float* w_out      = (const float*)d_in[6];  // [256,64]
    const float* b_out      = (const float*)d_in[7];  // [64]
    float* out = (float*)d_out;                       // [8,4096,64]

    float* xr = nullptr;
    float* zz = nullptr;
    float* hs = nullptr;
    cudaGetSymbolAddress((void**)&xr, g_xr);
    cudaGetSymbolAddress((void**)&zz, g_z);
    cudaGetSymbolAddress((void**)&hs, g_hs);

    const int M = BB * TT;  // 32768

    // 1) xr = x @ w_in + b_in       [32768,512] x [512,128]
    gemm_bias_kernel<128, 128, 8, 8, 8, 256>
        <<<dim3(CC / 128, M / 128), 256>>>(x, w_in, b_in, xr, M, CC, FF);

    // 2) z = xr @ kernel + bias     [32768,128] x [128,1024]
    gemm_bias_kernel<128, 128, 8, 8, 8, 256>
        <<<dim3(G4 / 128, M / 128), 256>>>(xr, kern, bias, zz, M, G4, CC);

    // 3) LSTM recurrence: 8 clusters x 8 CTAs
    lstm_kernel<<<BB * CLSZ, LSTM_NTH>>>(rec_kernel);

    // 4) out = hs @ w_out + b_out   [32768,256] x [256,64]
    gemm_bias_kernel<128, 64, 8, 8, 4, 256>
        <<<dim3(OO / 64, M / 128), 256>>>(hs, w_out, b_out, out, M, OO, UU);
}